// round 12
// baseline (speedup 1.0000x reference)
#include <cuda_runtime.h>
#include <cuda_bf16.h>
#include <cstdint>
#include <cstddef>

#define BB 2
#define SS 2048
#define DD 1024
#define HH 16
#define DHH 64
#define WINDOW 256
#define MM (BB * SS)        // 4096 activation rows
#define K3 3072             // 3-way split K
#define NST 96              // K3 / 32 pipeline stages

// ---------------- scratch (__device__ globals; no allocs allowed) ----------
__device__ __nv_bfloat16 g_qh[(size_t)MM * DD];   // projected Q hi (pre-scaled 0.125)
__device__ __nv_bfloat16 g_ql[(size_t)MM * DD];
__device__ __nv_bfloat16 g_kh[(size_t)MM * DD];
__device__ __nv_bfloat16 g_kl[(size_t)MM * DD];
__device__ __nv_bfloat16 g_vh[(size_t)MM * DD];
__device__ __nv_bfloat16 g_vl[(size_t)MM * DD];
__device__ __nv_bfloat16 g_a2q[(size_t)MM * K3];  // split activations per proj
__device__ __nv_bfloat16 g_a2k[(size_t)MM * K3];
__device__ __nv_bfloat16 g_a2v[(size_t)MM * K3];
__device__ __nv_bfloat16 g_a2o[(size_t)MM * K3];  // attention out (O-proj A)
__device__ __nv_bfloat16 g_w2q[(size_t)DD * K3];  // split weights
__device__ __nv_bfloat16 g_w2k[(size_t)DD * K3];
__device__ __nv_bfloat16 g_w2v[(size_t)DD * K3];
__device__ __nv_bfloat16 g_w2o[(size_t)DD * K3];

// ---------------- PTX helpers ----------------------------------------------
__device__ __forceinline__ uint32_t smem_u32(const void* p) {
    uint32_t a;
    asm("{ .reg .u64 t; cvta.to.shared.u64 t, %1; cvt.u32.u64 %0, t; }"
        : "=r"(a) : "l"(p));
    return a;
}
__device__ __forceinline__ void cp_async16(uint32_t saddr, const void* gaddr) {
    asm volatile("cp.async.cg.shared.global [%0], [%1], 16;"
                 :: "r"(saddr), "l"(gaddr));
}
#define CP_COMMIT() asm volatile("cp.async.commit_group;" ::: "memory")
#define CP_WAIT2()  asm volatile("cp.async.wait_group 2;" ::: "memory")
#define CP_WAIT0()  asm volatile("cp.async.wait_group 0;" ::: "memory")

__device__ __forceinline__ void ldmatrix_x4(uint32_t* r, uint32_t addr) {
    asm volatile("ldmatrix.sync.aligned.m8n8.x4.shared.b16 {%0,%1,%2,%3}, [%4];"
                 : "=r"(r[0]), "=r"(r[1]), "=r"(r[2]), "=r"(r[3]) : "r"(addr));
}
__device__ __forceinline__ void ldmatrix_x4_trans(uint32_t* r, uint32_t addr) {
    asm volatile("ldmatrix.sync.aligned.m8n8.x4.trans.shared.b16 {%0,%1,%2,%3}, [%4];"
                 : "=r"(r[0]), "=r"(r[1]), "=r"(r[2]), "=r"(r[3]) : "r"(addr));
}
__device__ __forceinline__ void mma_bf16(float* d, const uint32_t* a,
                                         uint32_t b0, uint32_t b1) {
    asm volatile(
        "mma.sync.aligned.m16n8k16.row.col.f32.bf16.bf16.f32 "
        "{%0,%1,%2,%3}, {%4,%5,%6,%7}, {%8,%9}, {%0,%1,%2,%3};"
        : "+f"(d[0]), "+f"(d[1]), "+f"(d[2]), "+f"(d[3])
        : "r"(a[0]), "r"(a[1]), "r"(a[2]), "r"(a[3]), "r"(b0), "r"(b1));
}
__device__ __forceinline__ uint32_t pack_bf16x2(float a, float b) {
    __nv_bfloat162 t;
    t.x = __float2bfloat16(a);
    t.y = __float2bfloat16(b);
    return *(uint32_t*)&t;
}
__device__ __forceinline__ uint32_t pack_hi_lo(float a, float b, uint32_t& lo) {
    __nv_bfloat16 ha = __float2bfloat16(a), hb = __float2bfloat16(b);
    lo = pack_bf16x2(a - __bfloat162float(ha), b - __bfloat162float(hb));
    __nv_bfloat162 t; t.x = ha; t.y = hb;
    return *(uint32_t*)&t;
}

// ---------------------------------------------------------------------------
// Fused prep: all 7 splits in one launch.
// grid (4096, 7): y=0..3 -> Wq/Wk/Wv/Wo [hi|hi|lo] (1024 rows, extra exit);
//                 y=4..6 -> query/key/value [hi|lo|hi] (4096 rows).
// block 256: thread = one float4 of the row.
// ---------------------------------------------------------------------------
__global__ void prep_kernel(const float* __restrict__ query,
                            const float* __restrict__ key,
                            const float* __restrict__ value,
                            const float* __restrict__ Wq,
                            const float* __restrict__ Wk,
                            const float* __restrict__ Wv,
                            const float* __restrict__ Wo)
{
    const int y = blockIdx.y;
    const int row = blockIdx.x;
    const float* in;
    __nv_bfloat16* out;
    bool amode;
    if (y < 4) {
        if (row >= DD) return;
        amode = false;
        in  = (y == 0) ? Wq : (y == 1) ? Wk : (y == 2) ? Wv : Wo;
        out = (y == 0) ? g_w2q : (y == 1) ? g_w2k : (y == 2) ? g_w2v : g_w2o;
    } else {
        amode = true;
        in  = (y == 4) ? query : (y == 5) ? key : value;
        out = (y == 4) ? g_a2q : (y == 5) ? g_a2k : g_a2v;
    }
    const int c4 = threadIdx.x;            // 0..255 float4s
    float4 f = ((const float4*)in)[(size_t)row * 256 + c4];

    uint32_t lA, lB;
    uint32_t hA = pack_hi_lo(f.x, f.y, lA);
    uint32_t hB = pack_hi_lo(f.z, f.w, lB);

    size_t base = (size_t)row * K3 + c4 * 4;
    uint32_t* o0 = (uint32_t*)(out + base);
    uint32_t* o1 = (uint32_t*)(out + base + 1024);
    uint32_t* o2 = (uint32_t*)(out + base + 2048);
    o0[0] = hA; o0[1] = hB;
    if (amode) { o1[0] = lA; o1[1] = lB; o2[0] = hA; o2[1] = hB; }
    else       { o1[0] = hA; o1[1] = hB; o2[0] = lA; o2[1] = lB; }
}

// ---------------------------------------------------------------------------
// Shared GEMM body: C = A2[M,K3] @ W2[DD,K3]^T + bias
//   OSPLIT=0: fp32 store; OSPLIT=1: (v*oscale) -> bf16 hi/lo split stores
// ---------------------------------------------------------------------------
template <int OSPLIT>
__device__ __forceinline__ void gemm_body(
    const __nv_bfloat16* __restrict__ A2, const __nv_bfloat16* __restrict__ W2,
    const float* __restrict__ bias, float* __restrict__ C,
    __nv_bfloat16* __restrict__ Chi, __nv_bfloat16* __restrict__ Clo,
    float oscale, char* smem_raw)
{
    const uint32_t smem = smem_u32(smem_raw);

    const int tid  = threadIdx.x;
    const int wid  = tid >> 5;
    const int lane = tid & 31;
    const int wm = wid & 1;
    const int wn = wid >> 1;
    const int n0 = blockIdx.x * 128;
    const int m0 = blockIdx.y * 128;

    const __nv_bfloat16* Abase = A2 + (size_t)m0 * K3;
    const __nv_bfloat16* Wbase = W2 + (size_t)n0 * K3;

    const int cl0 = tid;
    const int cl1 = tid + 256;
    const int lr0 = cl0 >> 2, lc0 = cl0 & 3;
    const int lr1 = cl1 >> 2, lc1 = cl1 & 3;
    const uint32_t so0 = lr0 * 64 + ((lc0 ^ ((lr0 >> 1) & 3)) << 4);
    const uint32_t so1 = lr1 * 64 + ((lc1 ^ ((lr1 >> 1) & 3)) << 4);

    const int lane15 = lane & 15;
    const int hib = lane >> 4;
    uint32_t a_off[4], b_off[2];
    int a_sw[4], b_sw[2];
#pragma unroll
    for (int mt = 0; mt < 4; mt++) {
        int r = wm * 64 + mt * 16 + lane15;
        a_off[mt] = r * 64;
        a_sw[mt] = (r >> 1) & 3;
    }
#pragma unroll
    for (int bp = 0; bp < 2; bp++) {
        int r = wn * 32 + bp * 16 + lane15;
        b_off[bp] = 8192 + r * 64;
        b_sw[bp] = (r >> 1) & 3;
    }

    float d[4][4][4];
#pragma unroll
    for (int mt = 0; mt < 4; mt++)
#pragma unroll
        for (int nt = 0; nt < 4; nt++)
#pragma unroll
            for (int j = 0; j < 4; j++) d[mt][nt][j] = 0.f;

#pragma unroll
    for (int st = 0; st < 3; st++) {
        uint32_t sb = smem + (st & 3) * 16384;
        const __nv_bfloat16* Ag = Abase + st * 32;
        const __nv_bfloat16* Wg = Wbase + st * 32;
        cp_async16(sb + so0,        Ag + (size_t)lr0 * K3 + lc0 * 8);
        cp_async16(sb + 8192 + so0, Wg + (size_t)lr0 * K3 + lc0 * 8);
        cp_async16(sb + so1,        Ag + (size_t)lr1 * K3 + lc1 * 8);
        cp_async16(sb + 8192 + so1, Wg + (size_t)lr1 * K3 + lc1 * 8);
        CP_COMMIT();
    }

    for (int st = 0; st < NST; st++) {
        CP_WAIT2();
        __syncthreads();

        int pf = st + 3;
        if (pf < NST) {
            uint32_t sb = smem + (pf & 3) * 16384;
            const __nv_bfloat16* Ag = Abase + pf * 32;
            const __nv_bfloat16* Wg = Wbase + pf * 32;
            cp_async16(sb + so0,        Ag + (size_t)lr0 * K3 + lc0 * 8);
            cp_async16(sb + 8192 + so0, Wg + (size_t)lr0 * K3 + lc0 * 8);
            cp_async16(sb + so1,        Ag + (size_t)lr1 * K3 + lc1 * 8);
            cp_async16(sb + 8192 + so1, Wg + (size_t)lr1 * K3 + lc1 * 8);
        }
        CP_COMMIT();

        uint32_t base = smem + (st & 3) * 16384;
#pragma unroll
        for (int s16 = 0; s16 < 2; s16++) {
            int ch = s16 * 2 + hib;
            uint32_t a[4][4], bb[2][4];
#pragma unroll
            for (int mt = 0; mt < 4; mt++)
                ldmatrix_x4(a[mt], base + a_off[mt] + ((ch ^ a_sw[mt]) << 4));
#pragma unroll
            for (int bp = 0; bp < 2; bp++)
                ldmatrix_x4(bb[bp], base + b_off[bp] + ((ch ^ b_sw[bp]) << 4));
#pragma unroll
            for (int mt = 0; mt < 4; mt++)
#pragma unroll
                for (int nt = 0; nt < 4; nt++)
                    mma_bf16(d[mt][nt], a[mt],
                             bb[nt >> 1][nt & 1],
                             bb[nt >> 1][(nt & 1) + 2]);
        }
    }

    const int ncol0 = n0 + wn * 32 + (lane & 3) * 2;
    const int mrow0 = m0 + wm * 64 + (lane >> 2);
#pragma unroll
    for (int nt = 0; nt < 4; nt++) {
        float2 bv = *(const float2*)(bias + ncol0 + nt * 8);
#pragma unroll
        for (int mt = 0; mt < 4; mt++) {
            int r1 = mrow0 + mt * 16;
            float v0 = (d[mt][nt][0] + bv.x) * oscale;
            float v1 = (d[mt][nt][1] + bv.y) * oscale;
            float v2 = (d[mt][nt][2] + bv.x) * oscale;
            float v3 = (d[mt][nt][3] + bv.y) * oscale;
            if (OSPLIT) {
                uint32_t lo0, lo1;
                uint32_t hi0 = pack_hi_lo(v0, v1, lo0);
                uint32_t hi1 = pack_hi_lo(v2, v3, lo1);
                size_t p0 = (size_t)r1 * DD + ncol0 + nt * 8;
                size_t p1 = (size_t)(r1 + 8) * DD + ncol0 + nt * 8;
                *(uint32_t*)(Chi + p0) = hi0;
                *(uint32_t*)(Clo + p0) = lo0;
                *(uint32_t*)(Chi + p1) = hi1;
                *(uint32_t*)(Clo + p1) = lo1;
            } else {
                *(float2*)(C + (size_t)r1 * DD + ncol0 + nt * 8) =
                    make_float2(v0, v1);
                *(float2*)(C + (size_t)(r1 + 8) * DD + ncol0 + nt * 8) =
                    make_float2(v2, v3);
            }
        }
    }
}

// Fused QKV projections: blockIdx.z selects {Q,K,V}. 768 CTAs -> 2.6 waves.
__global__ __launch_bounds__(256, 2)
void gemm_qkv_kernel(const float* __restrict__ bq,
                     const float* __restrict__ bk,
                     const float* __restrict__ bv)
{
    extern __shared__ char smem_raw[];
    const int z = blockIdx.z;
    const __nv_bfloat16* A2 = (z == 0) ? g_a2q : (z == 1) ? g_a2k : g_a2v;
    const __nv_bfloat16* W2 = (z == 0) ? g_w2q : (z == 1) ? g_w2k : g_w2v;
    const float* bias = (z == 0) ? bq : (z == 1) ? bk : bv;
    __nv_bfloat16* Chi = (z == 0) ? g_qh : (z == 1) ? g_kh : g_vh;
    __nv_bfloat16* Clo = (z == 0) ? g_ql : (z == 1) ? g_kl : g_vl;
    float oscale = (z == 0) ? 0.125f : 1.0f;
    gemm_body<1>(A2, W2, bias, nullptr, Chi, Clo, oscale, smem_raw);
}

// Output projection
__global__ __launch_bounds__(256, 2)
void gemm_o_kernel(const float* __restrict__ bo, float* __restrict__ C)
{
    extern __shared__ char smem_raw[];
    gemm_body<0>(g_a2o, g_w2o, bo, C, nullptr, nullptr, 1.0f, smem_raw);
}

// ---------------------------------------------------------------------------
// Tensor-core windowed flash attention (R11) + masked-MMA skipping:
//   phase kb=4 (causal): warp w computes j < 2w+2 (QK), kc < w+1 (PV)
//   phase kb=0 (window edge, q0>=256): j >= 2w, kc >= w
// Skipping is exact: skipped QK tiles are fully masked (-1e4 overwrite);
// skipped PV chunks have P == 0.
// ---------------------------------------------------------------------------
#define ATT_SMEM (6 * 8192)   // Qh Ql Kh Kl Vh Vl

__global__ __launch_bounds__(128, 3)
void attn_tc_kernel()
{
    extern __shared__ __nv_bfloat16 smb[];
    const uint32_t sQh = smem_u32(smb);
    const uint32_t sQl = sQh + 8192;
    const uint32_t sKh = sQh + 16384;
    const uint32_t sKl = sQh + 24576;
    const uint32_t sVh = sQh + 32768;
    const uint32_t sVl = sQh + 40960;

    const int tid = threadIdx.x;
    const int w = tid >> 5;
    const int lane = tid & 31;
    const int lane15 = lane & 15;
    const int hib = lane >> 4;
    const int qt = blockIdx.x;
    const int bh = blockIdx.y;
    const int b = bh >> 4;
    const int h = bh & 15;
    const int q0 = qt * 64;

    const size_t gbase = (size_t)(b * SS) * DD + h * DHH;

#pragma unroll
    for (int t = 0; t < 4; t++) {
        int q = tid + t * 128;
        int row = q >> 3, ch = q & 7;
        uint32_t off = row * 128 + ((ch ^ (row & 7)) << 4);
        cp_async16(sQh + off, g_qh + gbase + (size_t)(q0 + row) * DD + ch * 8);
        cp_async16(sQl + off, g_ql + gbase + (size_t)(q0 + row) * DD + ch * 8);
    }
    CP_COMMIT();
    CP_WAIT0();
    __syncthreads();

    uint32_t qh[4][4], ql[4][4];
    {
        int ar = w * 16 + lane15;
#pragma unroll
        for (int kc = 0; kc < 4; kc++) {
            uint32_t off = ar * 128 + (((kc * 2 + hib) ^ (ar & 7)) << 4);
            ldmatrix_x4(qh[kc], sQh + off);
            ldmatrix_x4(ql[kc], sQl + off);
        }
    }

    const int r0 = q0 + w * 16 + (lane >> 2);
    const int r1 = r0 + 8;

    float o[8][4];
#pragma unroll
    for (int j = 0; j < 8; j++)
#pragma unroll
        for (int x = 0; x < 4; x++) o[j][x] = 0.f;
    float m0r = -1e30f, m1r = -1e30f, l0r = 0.f, l1r = 0.f;

    for (int kb = 0; kb < 5; kb++) {
        int kstart = q0 - 256 + kb * 64;
        if (kstart < 0) continue;

        // per-warp valid tile bounds for boundary phases
        int jlo = 0, jhi = 8, klo = 0, khi = 4;
        if (kb == 4)      { jhi = 2 * w + 2; khi = w + 1; }   // causal triangle
        else if (kb == 0) { jlo = 2 * w;     klo = w; }       // window edge

        __syncthreads();
#pragma unroll
        for (int t = 0; t < 4; t++) {
            int q = tid + t * 128;
            int row = q >> 3, ch = q & 7;
            uint32_t off = row * 128 + ((ch ^ (row & 7)) << 4);
            size_t gs = gbase + (size_t)(kstart + row) * DD + ch * 8;
            cp_async16(sKh + off, g_kh + gs);
            cp_async16(sKl + off, g_kl + gs);
            cp_async16(sVh + off, g_vh + gs);
            cp_async16(sVl + off, g_vl + gs);
        }
        CP_COMMIT();
        CP_WAIT0();
        __syncthreads();

        // ---- S = Q @ K^T (3-term), skipping fully-masked j tiles ----
        float s[8][4];
#pragma unroll
        for (int j = 0; j < 8; j++)
#pragma unroll
            for (int x = 0; x < 4; x++) s[j][x] = 0.f;

#pragma unroll
        for (int kc = 0; kc < 4; kc++) {
            uint32_t kh[4][4], kl[4][4];
#pragma unroll
            for (int ng = 0; ng < 4; ng++) {
                if (ng < (jlo >> 1) || ng > ((jhi - 1) >> 1)) continue;
                int br = ng * 16 + lane15;
                uint32_t off = br * 128 + (((kc * 2 + hib) ^ (br & 7)) << 4);
                ldmatrix_x4(kh[ng], sKh + off);
                ldmatrix_x4(kl[ng], sKl + off);
            }
#pragma unroll
            for (int j = 0; j < 8; j++) {
                if (j < jlo || j >= jhi) continue;
                uint32_t b0h = kh[j >> 1][j & 1], b1h = kh[j >> 1][(j & 1) + 2];
                uint32_t b0l = kl[j >> 1][j & 1], b1l = kl[j >> 1][(j & 1) + 2];
                mma_bf16(s[j], qh[kc], b0h, b1h);
                mma_bf16(s[j], ql[kc], b0h, b1h);
                mma_bf16(s[j], qh[kc], b0l, b1l);
            }
        }

        // ---- mask + online softmax (unconditional; covers skipped tiles) ----
        const int cb = kstart + 2 * (lane & 3);
#pragma unroll
        for (int j = 0; j < 8; j++) {
            int c0 = cb + 8 * j, c1 = c0 + 1;
            if (!(c0 <= r0 && c0 >= r0 - (WINDOW - 1))) s[j][0] = -1e4f;
            if (!(c1 <= r0 && c1 >= r0 - (WINDOW - 1))) s[j][1] = -1e4f;
            if (!(c0 <= r1 && c0 >= r1 - (WINDOW - 1))) s[j][2] = -1e4f;
            if (!(c1 <= r1 && c1 >= r1 - (WINDOW - 1))) s[j][3] = -1e4f;
        }
        float ml0 = -1e30f, ml1 = -1e30f;
#pragma unroll
        for (int j = 0; j < 8; j++) {
            ml0 = fmaxf(ml0, fmaxf(s[j][0], s[j][1]));
            ml1 = fmaxf(ml1, fmaxf(s[j][2], s[j][3]));
        }
        ml0 = fmaxf(ml0, __shfl_xor_sync(0xffffffffu, ml0, 1));
        ml0 = fmaxf(ml0, __shfl_xor_sync(0xffffffffu, ml0, 2));
        ml1 = fmaxf(ml1, __shfl_xor_sync(0xffffffffu, ml1, 1));
        ml1 = fmaxf(ml1, __shfl_xor_sync(0xffffffffu, ml1, 2));
        float mn0 = fmaxf(m0r, ml0), mn1 = fmaxf(m1r, ml1);
        float fac0 = __expf(m0r - mn0), fac1 = __expf(m1r - mn1);
        float ps0 = 0.f, ps1 = 0.f;
#pragma unroll
        for (int j = 0; j < 8; j++) {
            s[j][0] = __expf(s[j][0] - mn0);
            s[j][1] = __expf(s[j][1] - mn0);
            s[j][2] = __expf(s[j][2] - mn1);
            s[j][3] = __expf(s[j][3] - mn1);
            ps0 += s[j][0] + s[j][1];
            ps1 += s[j][2] + s[j][3];
        }
        ps0 += __shfl_xor_sync(0xffffffffu, ps0, 1);
        ps0 += __shfl_xor_sync(0xffffffffu, ps0, 2);
        ps1 += __shfl_xor_sync(0xffffffffu, ps1, 1);
        ps1 += __shfl_xor_sync(0xffffffffu, ps1, 2);
        l0r = l0r * fac0 + ps0;  m0r = mn0;
        l1r = l1r * fac1 + ps1;  m1r = mn1;
#pragma unroll
        for (int j = 0; j < 8; j++) {
            o[j][0] *= fac0; o[j][1] *= fac0;
            o[j][2] *= fac1; o[j][3] *= fac1;
        }

        // ---- pack P fragments (only live kc chunks) ----
        uint32_t phi[4][4], plo[4][4];
#pragma unroll
        for (int kc = 0; kc < 4; kc++) {
            if (kc < klo || kc >= khi) continue;
            phi[kc][0] = pack_hi_lo(s[2 * kc][0],     s[2 * kc][1],     plo[kc][0]);
            phi[kc][1] = pack_hi_lo(s[2 * kc][2],     s[2 * kc][3],     plo[kc][1]);
            phi[kc][2] = pack_hi_lo(s[2 * kc + 1][0], s[2 * kc + 1][1], plo[kc][2]);
            phi[kc][3] = pack_hi_lo(s[2 * kc + 1][2], s[2 * kc + 1][3], plo[kc][3]);
        }

        // ---- O += P @ V (3-term), skipping all-zero-P key chunks ----
#pragma unroll
        for (int kc = 0; kc < 4; kc++) {
            if (kc < klo || kc >= khi) continue;
            uint32_t vh[4][4], vl[4][4];
            int vr = kc * 16 + lane15;
#pragma unroll
            for (int ng = 0; ng < 4; ng++) {
                uint32_t off = vr * 128 + (((ng * 2 + hib) ^ (vr & 7)) << 4);
                ldmatrix_x4_trans(vh[ng], sVh + off);
                ldmatrix_x4_trans(vl[ng], sVl + off);
            }
#pragma unroll
            for (int j = 0; j < 8; j++) {
                uint32_t b0h = vh[j >> 1][(j & 1) * 2];
                uint32_t b1h = vh[j >> 1][(j & 1) * 2 + 1];
                uint32_t b0l = vl[j >> 1][(j & 1) * 2];
                uint32_t b1l = vl[j >> 1][(j & 1) * 2 + 1];
                mma_bf16(o[j], phi[kc], b0h, b1h);
                mma_bf16(o[j], plo[kc], b0h, b1h);
                mma_bf16(o[j], phi[kc], b0l, b1l);
            }
        }
    }

    // ---- epilogue: /l, split-write g_a2o [hi|lo|hi] ----
    float inv0 = 1.f / l0r, inv1 = 1.f / l1r;
    const int colbase = h * DHH + 2 * (lane & 3);
#pragma unroll
    for (int j = 0; j < 8; j++) {
        int col = colbase + 8 * j;
        float a0 = o[j][0] * inv0, a1 = o[j][1] * inv0;
        float a2 = o[j][2] * inv1, a3 = o[j][3] * inv1;
        uint32_t lo0, lo1;
        uint32_t hi0 = pack_hi_lo(a0, a1, lo0);
        uint32_t hi1 = pack_hi_lo(a2, a3, lo1);
        size_t base0 = (size_t)(b * SS + r0) * K3 + col;
        size_t base1 = (size_t)(b * SS + r1) * K3 + col;
        *(uint32_t*)(g_a2o + base0)        = hi0;
        *(uint32_t*)(g_a2o + base0 + 1024) = lo0;
        *(uint32_t*)(g_a2o + base0 + 2048) = hi0;
        *(uint32_t*)(g_a2o + base1)        = hi1;
        *(uint32_t*)(g_a2o + base1 + 1024) = lo1;
        *(uint32_t*)(g_a2o + base1 + 2048) = hi1;
    }
}

// ---------------------------------------------------------------------------
extern "C" void kernel_launch(void* const* d_in, const int* in_sizes, int n_in,
                              void* d_out, int out_size)
{
    (void)in_sizes; (void)n_in; (void)out_size;
    const float* query = (const float*)d_in[0];
    const float* key   = (const float*)d_in[1];
    const float* value = (const float*)d_in[2];
    const float* Wq = (const float*)d_in[3];
    const float* bq = (const float*)d_in[4];
    const float* Wk = (const float*)d_in[5];
    const float* bk = (const float*)d_in[6];
    const float* Wv = (const float*)d_in[7];
    const float* bv = (const float*)d_in[8];
    const float* Wo = (const float*)d_in[9];
    const float* bo = (const float*)d_in[10];
    float* out = (float*)d_out;

    const int SMEM_GEMM = 4 * 16384;
    cudaFuncSetAttribute(gemm_qkv_kernel,
                         cudaFuncAttributeMaxDynamicSharedMemorySize, SMEM_GEMM);
    cudaFuncSetAttribute(gemm_o_kernel,
                         cudaFuncAttributeMaxDynamicSharedMemorySize, SMEM_GEMM);
    cudaFuncSetAttribute(attn_tc_kernel,
                         cudaFuncAttributeMaxDynamicSharedMemorySize, ATT_SMEM);

    // 1. all splits (4 weights + 3 activations) in one launch
    prep_kernel<<<dim3(MM, 7), 256>>>(query, key, value, Wq, Wk, Wv, Wo);

    // 2. fused Q/K/V projection GEMMs (z selects projection)
    gemm_qkv_kernel<<<dim3(DD / 128, MM / 128, 3), 256, SMEM_GEMM>>>(bq, bk, bv);

    // 3. tensor-core windowed attention -> split activations g_a2o
    attn_tc_kernel<<<dim3(SS / 64, BB * HH), 128, ATT_SMEM>>>();

    // 4. output projection
    gemm_o_kernel<<<dim3(DD / 128, MM / 128), 256, SMEM_GEMM>>>(bo, out);
}